// round 3
// baseline (speedup 1.0000x reference)
#include <cuda_runtime.h>
#include <cuda_bf16.h>
#include <cstdint>
#include <cstddef>

#define DEV __device__ __forceinline__

// ---------------- problem dims (fixed by the dataset) ----------------
#define BB 64
#define TT 256
#define DDIM 1024
#define HDIM 4096
#define MM (BB*TT)                        // 16384 rows
#define N1  ((long long)MM * DDIM)        // 16,777,216
#define N2  ((long long)MM * HDIM)        // 67,108,864
#define NW1 ((long long)HDIM * DDIM)      // 4,194,304
#define NW2 ((long long)DDIM * HDIM)      // 4,194,304

// rank constants: nearest-rank for quantile(0.995) over n elements (0-based)
#define RANK1 16693329LL                  // round(0.995*(N1-1))
#define RANK2 66773319LL                  // round(0.995*(N2-1))

// ---------------- device scratch (allocation-free rule) ----------------
__device__ float          g_h1 [(size_t)N1];     // LN output fp32
__device__ __nv_bfloat16  g_h1q[(size_t)N1];     // quantized acts (exact ints)
__device__ float          g_a2 [(size_t)N2];     // GELU output fp32
__device__ __nv_bfloat16  g_a2q[(size_t)N2];     // quantized acts
__device__ __nv_bfloat16  g_w1q[(size_t)NW1];    // ternary w1 (exact -1/0/1)
__device__ __nv_bfloat16  g_w2q[(size_t)NW2];    // ternary w2

// select / scale state
__device__ unsigned  g_bins[2048];
__device__ unsigned  g_prefix;
__device__ unsigned  g_prefmask;
__device__ long long g_rank;
__device__ float     g_s[2];        // s = 127 / amax
__device__ float     g_gamma[2];    // gamma = mean|w| + 1e-5
__device__ double    g_wpart[2][512];

// ---------------- helpers ----------------
DEV float ff_warp_sum(float v) {
    #pragma unroll
    for (int o = 16; o; o >>= 1) v += __shfl_xor_sync(0xffffffffu, v, o);
    return v;
}

DEV float ff_gelu(float x) {
    return 0.5f * x * (1.0f + erff(x * 0.70710678118654752440f));
}

DEV unsigned ff_pack_bf16(float a, float b) {
    __nv_bfloat162 p = __floats2bfloat162_rn(a, b);
    return *reinterpret_cast<unsigned*>(&p);
}

DEV void ff_cp_async16(void* sdst, const void* gsrc) {
    unsigned d = (unsigned)__cvta_generic_to_shared(sdst);
    asm volatile("cp.async.cg.shared.global [%0], [%1], 16;\n" :: "r"(d), "l"(gsrc));
}

// ---------------- layernorm: one block (256 thr) per row, two-pass ----------------
__global__ __launch_bounds__(256) void ff_ln_kernel(
    const float* __restrict__ x, const float* __restrict__ gam,
    const float* __restrict__ bet)
{
    int row = blockIdx.x;
    int tid = threadIdx.x, w = tid >> 5, l = tid & 31;
    const float4* xr = (const float4*)(x + (size_t)row * DDIM);
    float4 v = xr[tid];

    __shared__ float sh[8];
    __shared__ float s_mu, s_inv;

    // pass 1: mean
    float s = v.x + v.y + v.z + v.w;
    float ws = ff_warp_sum(s);
    if (l == 0) sh[w] = ws;
    __syncthreads();
    if (w == 0) {
        float a = (l < 8) ? sh[l] : 0.0f;
        a = ff_warp_sum(a);
        if (l == 0) s_mu = a * (1.0f / DDIM);
    }
    __syncthreads();
    float mu = s_mu;

    // pass 2: variance of (x - mu)
    float dx = v.x - mu, dy = v.y - mu, dz = v.z - mu, dw = v.w - mu;
    float ss = dx*dx + dy*dy + dz*dz + dw*dw;
    float wss = ff_warp_sum(ss);
    __syncthreads();
    if (l == 0) sh[w] = wss;
    __syncthreads();
    if (w == 0) {
        float a = (l < 8) ? sh[l] : 0.0f;
        a = ff_warp_sum(a);
        if (l == 0) s_inv = 1.0f / sqrtf(a * (1.0f / DDIM) + 1e-5f);
    }
    __syncthreads();
    float inv = s_inv;

    const float4* gr = (const float4*)gam;
    const float4* br = (const float4*)bet;
    float4 g4 = gr[tid], b4 = br[tid];
    float4 o;
    o.x = dx * inv * g4.x + b4.x;
    o.y = dy * inv * g4.y + b4.y;
    o.z = dz * inv * g4.z + b4.z;
    o.w = dw * inv * g4.w + b4.w;
    ((float4*)(g_h1 + (size_t)row * DDIM))[tid] = o;
}

// ---------------- weight gamma: deterministic two-stage mean(|w|) ----------------
__global__ __launch_bounds__(256) void ff_wabs_part(const float* __restrict__ w,
                                                    long long n, int idx)
{
    long long per = n / gridDim.x;
    long long s0 = (long long)blockIdx.x * per;
    double acc = 0.0;
    for (long long i = s0 + threadIdx.x; i < s0 + per; i += blockDim.x)
        acc += (double)fabsf(w[i]);
    __shared__ double sd[256];
    sd[threadIdx.x] = acc;
    __syncthreads();
    for (int o = 128; o; o >>= 1) {
        if (threadIdx.x < o) sd[threadIdx.x] += sd[threadIdx.x + o];
        __syncthreads();
    }
    if (threadIdx.x == 0) g_wpart[idx][blockIdx.x] = sd[0];
}

__global__ void ff_wgamma_final(long long n, int idx) {
    if (threadIdx.x == 0) {
        double s = 0.0;
        for (int i = 0; i < 512; i++) s += g_wpart[idx][i];
        g_gamma[idx] = (float)(s / (double)n) + 1e-5f;
    }
}

// ---------------- ternary weight quantize ----------------
__global__ __launch_bounds__(256) void ff_wquant(const float* __restrict__ w,
                                                 long long n4, int idx)
{
    float g = g_gamma[idx];
    __nv_bfloat16* out = idx ? g_w2q : g_w1q;
    long long stride = (long long)gridDim.x * blockDim.x;
    const float4* p = (const float4*)w;
    for (long long i = (long long)blockIdx.x * blockDim.x + threadIdx.x; i < n4; i += stride) {
        float4 v = p[i];
        float t0 = fminf(fmaxf(rintf(v.x / g), -1.0f), 1.0f);
        float t1 = fminf(fmaxf(rintf(v.y / g), -1.0f), 1.0f);
        float t2 = fminf(fmaxf(rintf(v.z / g), -1.0f), 1.0f);
        float t3 = fminf(fmaxf(rintf(v.w / g), -1.0f), 1.0f);
        uint2 o;
        o.x = ff_pack_bf16(t0, t1);
        o.y = ff_pack_bf16(t2, t3);
        ((uint2*)out)[i] = o;
    }
}

// ---------------- radix select (quantile) ----------------
__global__ void ff_init_select(long long rank) {
    if (threadIdx.x == 0) { g_rank = rank; g_prefix = 0u; g_prefmask = 0u; }
    for (int i = threadIdx.x; i < 2048; i += blockDim.x) g_bins[i] = 0u;
}

__global__ __launch_bounds__(256) void ff_hist(int which, long long n4,
                                               int shift, unsigned binmask)
{
    __shared__ unsigned sb[2048];
    for (int i = threadIdx.x; i < 2048; i += blockDim.x) sb[i] = 0u;
    __syncthreads();
    unsigned pref = g_prefix, pmask = g_prefmask;
    const float4* p = (const float4*)(which ? (const float*)g_a2 : (const float*)g_h1);
    long long stride = (long long)gridDim.x * blockDim.x;
    for (long long i = (long long)blockIdx.x * blockDim.x + threadIdx.x; i < n4; i += stride) {
        float4 v = p[i];
        unsigned u;
        u = __float_as_uint(fabsf(v.x)); if ((u & pmask) == pref) atomicAdd(&sb[(u >> shift) & binmask], 1u);
        u = __float_as_uint(fabsf(v.y)); if ((u & pmask) == pref) atomicAdd(&sb[(u >> shift) & binmask], 1u);
        u = __float_as_uint(fabsf(v.z)); if ((u & pmask) == pref) atomicAdd(&sb[(u >> shift) & binmask], 1u);
        u = __float_as_uint(fabsf(v.w)); if ((u & pmask) == pref) atomicAdd(&sb[(u >> shift) & binmask], 1u);
    }
    __syncthreads();
    for (int i = threadIdx.x; i < 2048; i += blockDim.x)
        if (sb[i]) atomicAdd(&g_bins[i], sb[i]);
}

__global__ void ff_scan(int shift, int nbins, int is_final, int sidx) {
    if (threadIdx.x == 0) {
        long long r = g_rank, cum = 0;
        int sel = nbins - 1;
        for (int b = 0; b < nbins; b++) {
            unsigned c = g_bins[b];
            if (cum + (long long)c > r) { sel = b; g_rank = r - cum; break; }
            cum += c;
        }
        unsigned pref = g_prefix | ((unsigned)sel << shift);
        if (is_final) {
            float amax = fmaxf(__uint_as_float(pref), 1e-5f);
            g_s[sidx] = 127.0f / amax;
        } else {
            g_prefix = pref;
            g_prefmask |= ((unsigned)(nbins - 1)) << shift;
        }
    }
    __syncthreads();
    for (int i = threadIdx.x; i < 2048; i += blockDim.x) g_bins[i] = 0u;
}

// ---------------- activation int8 fake-quant (keep ints, fold 1/s later) ----------------
__global__ __launch_bounds__(256) void ff_actquant(int which, long long n4) {
    float s = g_s[which];
    const float4* in = (const float4*)(which ? (const float*)g_a2 : (const float*)g_h1);
    uint2* out = (uint2*)(which ? g_a2q : g_h1q);
    long long stride = (long long)gridDim.x * blockDim.x;
    for (long long i = (long long)blockIdx.x * blockDim.x + threadIdx.x; i < n4; i += stride) {
        float4 v = in[i];
        float q0 = fminf(fmaxf(rintf(v.x * s), -128.0f), 127.0f);
        float q1 = fminf(fmaxf(rintf(v.y * s), -128.0f), 127.0f);
        float q2 = fminf(fmaxf(rintf(v.z * s), -128.0f), 127.0f);
        float q3 = fminf(fmaxf(rintf(v.w * s), -128.0f), 127.0f);
        uint2 o;
        o.x = ff_pack_bf16(q0, q1);
        o.y = ff_pack_bf16(q2, q3);
        out[i] = o;
    }
}

// ---------------- GEMM: C[M][N] = scale * A[M][K] x B[N][K]^T, optional GELU ----------------
DEV void ff_load_stage(const __nv_bfloat16* A, const __nv_bfloat16* Bw, int K,
                       int bm, int bn, int kt, unsigned char* sa, int tid)
{
    unsigned char* sb = sa + 8192;
    #pragma unroll
    for (int i = 0; i < 2; i++) {
        int c = tid + i * 256;
        int row = c >> 2, ch = c & 3;
        int sw = ch ^ ((row >> 1) & 3);
        ff_cp_async16(sa + (row * 4 + sw) * 16, A  + (size_t)(bm + row) * K + kt * 32 + ch * 8);
        ff_cp_async16(sb + (row * 4 + sw) * 16, Bw + (size_t)(bn + row) * K + kt * 32 + ch * 8);
    }
    asm volatile("cp.async.commit_group;\n");
}

template<bool GELU>
__global__ __launch_bounds__(256) void ff_gemm(int layer, float* __restrict__ Cext,
                                               int M, int N, int K, int sidx)
{
    const __nv_bfloat16* A  = layer ? g_a2q : g_h1q;
    const __nv_bfloat16* Bw = layer ? g_w2q : g_w1q;
    float* C = layer ? Cext : g_a2;

    __shared__ __align__(128) unsigned char smem[3 * 16384];
    const int tid  = threadIdx.x;
    const int lane = tid & 31, warp = tid >> 5;
    const int wm = warp >> 2, wn = warp & 3;     // 2 x 4 warp grid
    const int bm = blockIdx.y * 128, bn = blockIdx.x * 128;
    const int ktiles = K >> 5;

    float acc[4][4][4];
    #pragma unroll
    for (int a = 0; a < 4; a++)
        #pragma unroll
        for (int b = 0; b < 4; b++)
            #pragma unroll
            for (int c = 0; c < 4; c++) acc[a][b][c] = 0.0f;

    ff_load_stage(A, Bw, K, bm, bn, 0, smem + 0 * 16384, tid);
    ff_load_stage(A, Bw, K, bm, bn, 1, smem + 1 * 16384, tid);

    for (int kt = 0; kt < ktiles; kt++) {
        if (kt < ktiles - 1) asm volatile("cp.async.wait_group 1;\n" ::: "memory");
        else                 asm volatile("cp.async.wait_group 0;\n" ::: "memory");
        __syncthreads();
        if (kt + 2 < ktiles)
            ff_load_stage(A, Bw, K, bm, bn, kt + 2, smem + ((kt + 2) % 3) * 16384, tid);

        unsigned char* sa = smem + (kt % 3) * 16384;
        unsigned char* sb = sa + 8192;

        #pragma unroll
        for (int s = 0; s < 2; s++) {
            unsigned ar[4][4];
            #pragma unroll
            for (int mi = 0; mi < 4; mi++) {
                int row = wm * 64 + mi * 16 + ((lane >> 3) & 1) * 8 + (lane & 7);
                int ch  = (2 * s + (lane >> 4)) ^ ((row >> 1) & 3);
                unsigned addr = (unsigned)__cvta_generic_to_shared(sa + (row * 4 + ch) * 16);
                asm volatile("ldmatrix.sync.aligned.m8n8.x4.shared.b16 {%0,%1,%2,%3}, [%4];\n"
                    : "=r"(ar[mi][0]), "=r"(ar[mi][1]), "=r"(ar[mi][2]), "=r"(ar[mi][3])
                    : "r"(addr));
            }
            unsigned br[4][2];
            #pragma unroll
            for (int nj2 = 0; nj2 < 2; nj2++) {
                int row = wn * 32 + nj2 * 16 + ((lane >> 3) & 1) * 8 + (lane & 7);
                int ch  = (2 * s + (lane >> 4)) ^ ((row >> 1) & 3);
                unsigned addr = (unsigned)__cvta_generic_to_shared(sb + (row * 4 + ch) * 16);
                unsigned q0, q1, q2, q3;
                asm volatile("ldmatrix.sync.aligned.m8n8.x4.shared.b16 {%0,%1,%2,%3}, [%4];\n"
                    : "=r"(q0), "=r"(q1), "=r"(q2), "=r"(q3) : "r"(addr));
                br[2 * nj2][0] = q0;     br[2 * nj2][1] = q2;
                br[2 * nj2 + 1][0] = q1; br[2 * nj2 + 1][1] = q3;
            }
            #pragma unroll
            for (int mi = 0; mi < 4; mi++)
                #pragma unroll
                for (int nj = 0; nj < 4; nj++) {
                    asm volatile(
                        "mma.sync.aligned.m16n8k16.row.col.f32.bf16.bf16.f32 "
                        "{%0,%1,%2,%3},{%4,%5,%6,%7},{%8,%9},{%0,%1,%2,%3};\n"
                        : "+f"(acc[mi][nj][0]), "+f"(acc[mi][nj][1]),
                          "+f"(acc[mi][nj][2]), "+f"(acc[mi][nj][3])
                        : "r"(ar[mi][0]), "r"(ar[mi][1]), "r"(ar[mi][2]), "r"(ar[mi][3]),
                          "r"(br[nj][0]), "r"(br[nj][1]));
                }
        }
    }

    float scale = g_gamma[sidx] / g_s[sidx];
    #pragma unroll
    for (int mi = 0; mi < 4; mi++) {
        int r0 = bm + wm * 64 + mi * 16 + (lane >> 2);
        #pragma unroll
        for (int nj = 0; nj < 4; nj++) {
            int cc = bn + wn * 32 + nj * 8 + (lane & 3) * 2;
            float v0 = acc[mi][nj][0] * scale;
            float v1 = acc[mi][nj][1] * scale;
            float v2 = acc[mi][nj][2] * scale;
            float v3 = acc[mi][nj][3] * scale;
            if (GELU) { v0 = ff_gelu(v0); v1 = ff_gelu(v1); v2 = ff_gelu(v2); v3 = ff_gelu(v3); }
            float2 p0 = make_float2(v0, v1);
            float2 p1 = make_float2(v2, v3);
            *(float2*)(C + (size_t)r0 * N + cc) = p0;
            *(float2*)(C + (size_t)(r0 + 8) * N + cc) = p1;
        }
    }
}

// ---------------- launch ----------------
extern "C" void kernel_launch(void* const* d_in, const int* in_sizes, int n_in,
                              void* d_out, int out_size)
{
    const float* x    = (const float*)d_in[0];
    const float* ln_g = (const float*)d_in[1];
    const float* ln_b = (const float*)d_in[2];
    const float* w1   = (const float*)d_in[3];
    const float* w2   = (const float*)d_in[4];
    float* out = (float*)d_out;

    // LayerNorm
    ff_ln_kernel<<<MM, 256>>>(x, ln_g, ln_b);

    // Weight ternarization (both layers)
    ff_wabs_part<<<512, 256>>>(w1, NW1, 0);
    ff_wgamma_final<<<1, 32>>>(NW1, 0);
    ff_wquant<<<2048, 256>>>(w1, NW1 / 4, 0);
    ff_wabs_part<<<512, 256>>>(w2, NW2, 1);
    ff_wgamma_final<<<1, 32>>>(NW2, 1);
    ff_wquant<<<2048, 256>>>(w2, NW2 / 4, 1);

    // Quantile select #1 over |h1|
    ff_init_select<<<1, 256>>>(RANK1);
    ff_hist<<<2048, 256>>>(0, N1 / 4, 21, 2047);
    ff_scan<<<1, 256>>>(21, 2048, 0, 0);
    ff_hist<<<2048, 256>>>(0, N1 / 4, 10, 2047);
    ff_scan<<<1, 256>>>(10, 2048, 0, 0);
    ff_hist<<<2048, 256>>>(0, N1 / 4, 0, 1023);
    ff_scan<<<1, 256>>>(0, 1024, 1, 0);

    // Quantize acts #1, GEMM1 + GELU
    ff_actquant<<<4096, 256>>>(0, N1 / 4);
    ff_gemm<true><<<dim3(HDIM / 128, MM / 128), 256>>>(0, nullptr, MM, HDIM, DDIM, 0);

    // Quantile select #2 over |a2|
    ff_init_select<<<1, 256>>>(RANK2);
    ff_hist<<<4096, 256>>>(1, N2 / 4, 21, 2047);
    ff_scan<<<1, 256>>>(21, 2048, 0, 1);
    ff_hist<<<4096, 256>>>(1, N2 / 4, 10, 2047);
    ff_scan<<<1, 256>>>(10, 2048, 0, 1);
    ff_hist<<<4096, 256>>>(1, N2 / 4, 0, 1023);
    ff_scan<<<1, 256>>>(0, 1024, 1, 1);

    // Quantize acts #2, GEMM2 -> output
    ff_actquant<<<8192, 256>>>(1, N2 / 4);
    ff_gemm<false><<<dim3(DDIM / 128, MM / 128), 256>>>(1, out, MM, DDIM, HDIM, 1);
}